// round 5
// baseline (speedup 1.0000x reference)
#include <cuda_runtime.h>
#include <cstdint>

// Segment offsets scratch: offsets[n] = first edge index whose segment id >= n.
#define MAX_SEGMENTS 131072
__device__ int g_offsets[MAX_SEGMENTS + 1];
__device__ unsigned int g_cursor;    // dynamic work-stealing cursor (segments)

#define BATCH 4                      // segments per steal
#define BLOCK_THREADS 128
#define GRID_BLOCKS 1368             // ~9 CTAs/SM on 152 SMs (persistent, 1 wave)

// ---------------------------------------------------------------------------
// Kernel 1: streaming offsets builder (index is SORTED): thread e writes
// offsets[n] = e for n in (index[e-1], index[e]]; thread E-1 fills the tail.
// Also resets the steal cursor for the main kernel (same-stream ordering).
// Dtype robustness: JAX x64-off silently downcasts int64->int32; if truly
// int64 (values < 2^31) the low word sits at position 2m. Detect via 3
// trailing odd words (all zero iff int64 high halves).
// ---------------------------------------------------------------------------
__global__ void build_offsets_kernel(const unsigned int* __restrict__ w,
                                     int E, int N) {
    int e = blockIdx.x * blockDim.x + threadIdx.x;
    if (e == 0) g_cursor = 0;
    if (e >= E) return;

    int j = E - 1;
    if ((j & 1) == 0) j -= 1;
    unsigned int acc = 0;
    for (int k = 0; k < 3 && j - 2 * k >= 1; ++k)
        acc |= __ldg(&w[j - 2 * k]);
    const int shift = (acc == 0) ? 1 : 0;    // word index = m << shift

    int cur  = (int)__ldg(&w[((unsigned)e) << shift]);
    int prev = (e == 0) ? -1 : (int)__ldg(&w[((unsigned)(e - 1)) << shift]);

    for (int n = prev + 1; n <= cur; ++n)
        g_offsets[n] = e;

    if (e == E - 1) {
        for (int n = cur + 1; n <= N; ++n)
            g_offsets[n] = E;
    }
}

// ---------------------------------------------------------------------------
// Kernel 2: persistent warps + dynamic stealing. Each warp atomically grabs
// BATCH consecutive segments; the NEXT grab is issued before processing the
// current batch so the ATOMG latency (~318cyc) is hidden under the stream.
// Lane l owns float4 column 4l (D=128 -> one per lane). Rows unrolled x4
// for MLP; __ldcs read-once x stream, __stcs write-once output. Empty
// segments write zeros (output poisoned 0xAA).
// ---------------------------------------------------------------------------
__global__ void __launch_bounds__(BLOCK_THREADS, 9)
segment_mean_kernel(const float* __restrict__ x,
                    float* __restrict__ out,
                    int D, int N) {
    const int lane = threadIdx.x & 31;
    const int c = lane * 4;   // D == 128: one float4 column per lane

    unsigned cur = 0;
    if (lane == 0) cur = atomicAdd(&g_cursor, BATCH);
    cur = __shfl_sync(0xffffffffu, cur, 0);

    while (cur < (unsigned)N) {
        // Pipelined grab of the next batch (latency hidden by processing).
        unsigned nxt = 0;
        if (lane == 0) nxt = atomicAdd(&g_cursor, BATCH);
        nxt = __shfl_sync(0xffffffffu, nxt, 0);

        unsigned seg_end = cur + BATCH;
        if (seg_end > (unsigned)N) seg_end = (unsigned)N;

        int s = g_offsets[cur];
        for (unsigned seg = cur; seg < seg_end; ++seg) {
            int e = g_offsets[seg + 1];
            int cnt = e - s;
            float inv = (cnt > 0) ? (1.0f / (float)cnt) : 0.0f;

            float4 a0 = make_float4(0.f, 0.f, 0.f, 0.f);
            float4 a1 = make_float4(0.f, 0.f, 0.f, 0.f);
            float4 a2 = make_float4(0.f, 0.f, 0.f, 0.f);
            float4 a3 = make_float4(0.f, 0.f, 0.f, 0.f);

            const float* p = x + (size_t)s * D + c;
            int r = s;
            for (; r + 4 <= e; r += 4, p += 4 * D) {
                float4 v0 = __ldcs(reinterpret_cast<const float4*>(p));
                float4 v1 = __ldcs(reinterpret_cast<const float4*>(p + D));
                float4 v2 = __ldcs(reinterpret_cast<const float4*>(p + 2 * D));
                float4 v3 = __ldcs(reinterpret_cast<const float4*>(p + 3 * D));
                a0.x += v0.x; a0.y += v0.y; a0.z += v0.z; a0.w += v0.w;
                a1.x += v1.x; a1.y += v1.y; a1.z += v1.z; a1.w += v1.w;
                a2.x += v2.x; a2.y += v2.y; a2.z += v2.z; a2.w += v2.w;
                a3.x += v3.x; a3.y += v3.y; a3.z += v3.z; a3.w += v3.w;
            }
            for (; r < e; ++r, p += D) {
                float4 v0 = __ldcs(reinterpret_cast<const float4*>(p));
                a0.x += v0.x; a0.y += v0.y; a0.z += v0.z; a0.w += v0.w;
            }

            float4 res;
            res.x = ((a0.x + a1.x) + (a2.x + a3.x)) * inv;
            res.y = ((a0.y + a1.y) + (a2.y + a3.y)) * inv;
            res.z = ((a0.z + a1.z) + (a2.z + a3.z)) * inv;
            res.w = ((a0.w + a1.w) + (a2.w + a3.w)) * inv;
            __stcs(reinterpret_cast<float4*>(out + (size_t)seg * D + c), res);

            s = e;
        }
        cur = nxt;
    }
}

// ---------------------------------------------------------------------------
// Launch
// Inputs (metadata order): d_in[0] = x (float32, E*D), d_in[1] = index (E,
// int32 or int64 — detected on device), d_in[2] = dim_size (unused).
// ---------------------------------------------------------------------------
extern "C" void kernel_launch(void* const* d_in, const int* in_sizes, int n_in,
                              void* d_out, int out_size) {
    const float*        x   = (const float*)d_in[0];
    const unsigned int* idx = (const unsigned int*)d_in[1];
    float*              out = (float*)d_out;

    int E = in_sizes[1];          // 640000
    int D = in_sizes[0] / E;      // 128
    int N = out_size / D;         // 100000

    // Kernel 1: streaming segment boundaries + cursor reset (E threads).
    {
        int threads = 256;
        int blocks = (E + threads - 1) / threads;
        build_offsets_kernel<<<blocks, threads>>>(idx, E, N);
    }

    // Kernel 2: persistent dynamic-stealing reducer (~1 wave).
    segment_mean_kernel<<<GRID_BLOCKS, BLOCK_THREADS>>>(x, out, D, N);
}

// round 6
// speedup vs baseline: 1.0026x; 1.0026x over previous
#include <cuda_runtime.h>
#include <cstdint>

// Segment offsets scratch: offsets[n] = first edge index whose segment id >= n.
#define MAX_SEGMENTS 131072
__device__ int g_offsets[MAX_SEGMENTS + 1];
__device__ int g_shift;              // 1 if index is int64 (value in low word at 2m), 0 if int32

#define ROWS_PER_WARP 32
#define BLOCK_THREADS 128

// ---------------------------------------------------------------------------
// Kernel 1: streaming offsets builder (index is SORTED): thread e writes
// offsets[n] = e for n in (index[e-1], index[e]]; thread E-1 fills the tail.
// Also publishes the detected dtype shift for the main kernel.
// Dtype robustness: JAX x64-off silently downcasts int64->int32; if truly
// int64 (values < 2^31) the low word sits at position 2m. Detect via 3
// trailing odd words (all zero iff int64 high halves).
// ---------------------------------------------------------------------------
__global__ void build_offsets_kernel(const unsigned int* __restrict__ w,
                                     int E, int N) {
    int e = blockIdx.x * blockDim.x + threadIdx.x;
    if (e >= E) return;

    int j = E - 1;
    if ((j & 1) == 0) j -= 1;
    unsigned int acc = 0;
    for (int k = 0; k < 3 && j - 2 * k >= 1; ++k)
        acc |= __ldg(&w[j - 2 * k]);
    const int shift = (acc == 0) ? 1 : 0;    // word index = m << shift
    if (e == 0) g_shift = shift;

    int cur  = (int)__ldg(&w[((unsigned)e) << shift]);
    int prev = (e == 0) ? -1 : (int)__ldg(&w[((unsigned)(e - 1)) << shift]);

    for (int n = prev + 1; n <= cur; ++n)
        g_offsets[n] = e;

    if (e == E - 1) {
        for (int n = cur + 1; n <= N; ++n)
            g_offsets[n] = E;
    }
}

// ---------------------------------------------------------------------------
// Kernel 2: static EDGE-balanced partition, zero atomics. Warp w owns edge
// range [w*R, (w+1)*R) and therefore all segments whose start offset lies in
// that range: seg_lo = index[r0-1]+1 (0 for r0==0), seg_hi = index[r1-1]+1
// (N for the last range). Segment row ranges then exactly partition [0, E):
// every x row is read once, every segment written by exactly one warp, and
// per-warp work is R rows +/- one segment length -> occupancy-stable without
// the R5 cursor-atomic serialization or the R4 wave quantization.
// Lane l owns float4 column 4l (D=128). Rows unrolled x4 for MLP; __ldcs
// read-once stream, __stcs write-once output. Empty segments (cnt=0) write
// zeros (output poisoned 0xAA).
// ---------------------------------------------------------------------------
__global__ void __launch_bounds__(BLOCK_THREADS)
segment_mean_kernel(const float* __restrict__ x,
                    const unsigned int* __restrict__ iw,   // raw index words
                    float* __restrict__ out,
                    int D, int N, int E) {
    const int gwarp = (blockIdx.x * blockDim.x + threadIdx.x) >> 5;
    const int lane  = threadIdx.x & 31;
    const int c = lane * 4;   // D == 128: one float4 column per lane

    int r0 = gwarp * ROWS_PER_WARP;
    if (r0 >= E) return;
    int r1 = r0 + ROWS_PER_WARP;
    if (r1 > E) r1 = E;

    const int shift = g_shift;
    int seg_lo = (r0 == 0) ? 0 : (int)__ldg(&iw[((unsigned)(r0 - 1)) << shift]) + 1;
    int seg_hi = (r1 >= E) ? N : (int)__ldg(&iw[((unsigned)(r1 - 1)) << shift]) + 1;
    if (seg_lo >= seg_hi) return;

    int s = g_offsets[seg_lo];
    for (int seg = seg_lo; seg < seg_hi; ++seg) {
        int e = g_offsets[seg + 1];
        int cnt = e - s;
        float inv = (cnt > 0) ? (1.0f / (float)cnt) : 0.0f;

        float4 a0 = make_float4(0.f, 0.f, 0.f, 0.f);
        float4 a1 = make_float4(0.f, 0.f, 0.f, 0.f);
        float4 a2 = make_float4(0.f, 0.f, 0.f, 0.f);
        float4 a3 = make_float4(0.f, 0.f, 0.f, 0.f);

        const float* p = x + (size_t)s * D + c;
        int r = s;
        for (; r + 4 <= e; r += 4, p += 4 * D) {
            float4 v0 = __ldcs(reinterpret_cast<const float4*>(p));
            float4 v1 = __ldcs(reinterpret_cast<const float4*>(p + D));
            float4 v2 = __ldcs(reinterpret_cast<const float4*>(p + 2 * D));
            float4 v3 = __ldcs(reinterpret_cast<const float4*>(p + 3 * D));
            a0.x += v0.x; a0.y += v0.y; a0.z += v0.z; a0.w += v0.w;
            a1.x += v1.x; a1.y += v1.y; a1.z += v1.z; a1.w += v1.w;
            a2.x += v2.x; a2.y += v2.y; a2.z += v2.z; a2.w += v2.w;
            a3.x += v3.x; a3.y += v3.y; a3.z += v3.z; a3.w += v3.w;
        }
        for (; r < e; ++r, p += D) {
            float4 v0 = __ldcs(reinterpret_cast<const float4*>(p));
            a0.x += v0.x; a0.y += v0.y; a0.z += v0.z; a0.w += v0.w;
        }

        float4 res;
        res.x = ((a0.x + a1.x) + (a2.x + a3.x)) * inv;
        res.y = ((a0.y + a1.y) + (a2.y + a3.y)) * inv;
        res.z = ((a0.z + a1.z) + (a2.z + a3.z)) * inv;
        res.w = ((a0.w + a1.w) + (a2.w + a3.w)) * inv;
        __stcs(reinterpret_cast<float4*>(out + (size_t)seg * D + c), res);

        s = e;
    }
}

// ---------------------------------------------------------------------------
// Launch
// Inputs (metadata order): d_in[0] = x (float32, E*D), d_in[1] = index (E,
// int32 or int64 — detected on device), d_in[2] = dim_size (unused).
// ---------------------------------------------------------------------------
extern "C" void kernel_launch(void* const* d_in, const int* in_sizes, int n_in,
                              void* d_out, int out_size) {
    const float*        x   = (const float*)d_in[0];
    const unsigned int* idx = (const unsigned int*)d_in[1];
    float*              out = (float*)d_out;

    int E = in_sizes[1];          // 640000
    int D = in_sizes[0] / E;      // 128
    int N = out_size / D;         // 100000

    // Kernel 1: streaming segment boundaries + dtype shift (E threads).
    {
        int threads = 256;
        int blocks = (E + threads - 1) / threads;
        build_offsets_kernel<<<blocks, threads>>>(idx, E, N);
    }

    // Kernel 2: edge-balanced static partition, ROWS_PER_WARP rows per warp.
    {
        long long warps = ((long long)E + ROWS_PER_WARP - 1) / ROWS_PER_WARP;
        int warps_per_block = BLOCK_THREADS / 32;
        int blocks = (int)((warps + warps_per_block - 1) / warps_per_block);
        segment_mean_kernel<<<blocks, BLOCK_THREADS>>>(x, idx, out, D, N, E);
    }
}